// round 4
// baseline (speedup 1.0000x reference)
#include <cuda_runtime.h>

#define NN 100000
#define DD 128
#define EE 1600000
#define ND (NN * DD)

// ---------------- scratch (no allocation allowed -> __device__ globals) ----------------
__device__ float g_h[ND];          // 51.2 MB  current hidden state
__device__ float g_m[ND];          // 51.2 MB  m = h @ W_l
__device__ float g_agg[ND];        // 51.2 MB  segment-sum result
__device__ float g_gi[NN * 384];   // 153.6 MB gi = agg @ W_ih^T + b_ih
__device__ float g_gh[NN * 384];   // 153.6 MB gh = h   @ W_hh^T + b_hh
__device__ float g_Wt[DD * DD];    // transposed W_l (j-major)
__device__ int   g_src[EE];
__device__ int   g_dst[EE];
__device__ int   g_is64;

// ---------------- f32x2 helpers (B300 full-rate FP32 path) ----------------
__device__ __forceinline__ unsigned long long pack2(float x, float y) {
    unsigned long long r;
    asm("mov.b64 %0, {%1, %2};" : "=l"(r) : "f"(x), "f"(y));
    return r;
}
__device__ __forceinline__ void fma2(unsigned long long& d, unsigned long long a, unsigned long long b) {
    asm("fma.rn.f32x2 %0, %1, %2, %0;" : "+l"(d) : "l"(a), "l"(b));
}
__device__ __forceinline__ float2 unpack2(unsigned long long v) {
    float2 f;
    asm("mov.b64 {%0, %1}, %2;" : "=f"(f.x), "=f"(f.y) : "l"(v));
    return f;
}

// ---------------- small utility kernels ----------------
__global__ void copy4_kernel(float4* __restrict__ dst, const float4* __restrict__ src, int n4) {
    int i = blockIdx.x * blockDim.x + threadIdx.x;
    if (i < n4) dst[i] = src[i];
}
__global__ void zero4_kernel(float4* __restrict__ dst, int n4) {
    int i = blockIdx.x * blockDim.x + threadIdx.x;
    if (i < n4) dst[i] = make_float4(0.f, 0.f, 0.f, 0.f);
}

// Detect whether edge_index is int64 (high 32-bit words all zero since values < 100000) or int32.
__global__ void detect_kernel(const unsigned int* __restrict__ p) {
    if (blockIdx.x == 0 && threadIdx.x == 0) {
        unsigned long long s = 0;
        for (int i = 1; i < 2048; i += 2) s += p[i];
        g_is64 = (s == 0ull) ? 1 : 0;
    }
}
__global__ void conv_edges_kernel(const int* __restrict__ p) {
    int i = blockIdx.x * blockDim.x + threadIdx.x;
    if (i >= EE) return;
    if (g_is64) {
        g_src[i] = p[2 * i];
        g_dst[i] = p[2 * (EE + i)];
    } else {
        g_src[i] = p[i];
        g_dst[i] = p[EE + i];
    }
}

// Transpose one 128x128 W_l into j-major layout so all GEMMs use the K-contiguous form.
__global__ void transposeW_kernel(const float* __restrict__ Wl) {
    int i = blockIdx.x * blockDim.x + threadIdx.x;
    if (i < DD * DD) {
        int k = i >> 7, j = i & 127;
        g_Wt[j * 128 + k] = Wl[i];
    }
}

// ---------------- GEMM: C[m, j0+j] = sum_k A[m,k] * Bt[(j0+j)*128 + k] + bias[j] ----------------
// Tile 128(M) x 128(N), K chunked by 16. 256 threads, each owns 8 rows (paired for f32x2)
// x 8 cols (stride 16 for coalesced epilogue). Inner loop: 2 LDS.128 (A pairs) + 8 LDS.32 (B)
// + 8 packs + 32 fma.rn.f32x2 -> FMA2-pipe-bound. Register prefetch of next chunk hides LDG.
__launch_bounds__(256)
__global__ void gemm_bt_kernel(const float* __restrict__ A, const float* __restrict__ Bt,
                               const float* __restrict__ bias, float* __restrict__ C,
                               int M, int ldc) {
    __shared__ float As[16][132];   // [k][m], padded stride kills store conflicts
    __shared__ float Bs[16][132];   // [k][j]

    const int m0  = blockIdx.x * 128;
    const int j0  = blockIdx.y * 128;
    const int tid = threadIdx.x;
    const int tx  = tid & 15;       // col group: cols = j0 + tx + 16*jj
    const int ty  = tid >> 4;       // row group: rows = m0 + ty*8 .. +7

    // loader mapping: thread loads 2 float4 from one row (A) and one j-row (B)
    const int lm = tid >> 1;              // 0..127
    const int l0 = ((tid * 2) & 3) * 4;   // 0 or 8

    unsigned long long acc[8][4];
#pragma unroll
    for (int jj = 0; jj < 8; jj++) {
        float bj = bias ? __ldg(&bias[j0 + tx + 16 * jj]) : 0.f;
        unsigned long long b2 = pack2(bj, bj);
#pragma unroll
        for (int p = 0; p < 4; p++) acc[jj][p] = b2;
    }

    const bool arow_ok = (m0 + lm) < M;
    const float* Arow = A + (m0 + lm) * 128;
    const float* Brow = Bt + (j0 + lm) * 128;
    const float4 zf4 = make_float4(0.f, 0.f, 0.f, 0.f);

    // prefetch chunk 0
    float4 a0 = arow_ok ? *(const float4*)&Arow[l0]     : zf4;
    float4 a1 = arow_ok ? *(const float4*)&Arow[l0 + 4] : zf4;
    float4 b0 = *(const float4*)&Brow[l0];
    float4 b1 = *(const float4*)&Brow[l0 + 4];

    for (int c = 0; c < 8; c++) {
        __syncthreads();  // previous chunk's compute done
        As[l0 + 0][lm] = a0.x; As[l0 + 1][lm] = a0.y; As[l0 + 2][lm] = a0.z; As[l0 + 3][lm] = a0.w;
        As[l0 + 4][lm] = a1.x; As[l0 + 5][lm] = a1.y; As[l0 + 6][lm] = a1.z; As[l0 + 7][lm] = a1.w;
        Bs[l0 + 0][lm] = b0.x; Bs[l0 + 1][lm] = b0.y; Bs[l0 + 2][lm] = b0.z; Bs[l0 + 3][lm] = b0.w;
        Bs[l0 + 4][lm] = b1.x; Bs[l0 + 5][lm] = b1.y; Bs[l0 + 6][lm] = b1.z; Bs[l0 + 7][lm] = b1.w;
        __syncthreads();

        if (c < 7) {   // prefetch next chunk while computing this one
            int kn = (c + 1) * 16;
            a0 = arow_ok ? *(const float4*)&Arow[kn + l0]     : zf4;
            a1 = arow_ok ? *(const float4*)&Arow[kn + l0 + 4] : zf4;
            b0 = *(const float4*)&Brow[kn + l0];
            b1 = *(const float4*)&Brow[kn + l0 + 4];
        }

#pragma unroll
        for (int kk = 0; kk < 16; kk++) {
            ulonglong2 pa0 = *(const ulonglong2*)&As[kk][ty * 8];
            ulonglong2 pa1 = *(const ulonglong2*)&As[kk][ty * 8 + 4];
            unsigned long long ap0 = pa0.x, ap1 = pa0.y, ap2 = pa1.x, ap3 = pa1.y;
#pragma unroll
            for (int jj = 0; jj < 8; jj++) {
                float b = Bs[kk][tx + 16 * jj];
                unsigned long long b2 = pack2(b, b);
                fma2(acc[jj][0], ap0, b2);
                fma2(acc[jj][1], ap1, b2);
                fma2(acc[jj][2], ap2, b2);
                fma2(acc[jj][3], ap3, b2);
            }
        }
    }

    // epilogue: cols are tx-contiguous -> half-warp coalesced scalar stores
#pragma unroll
    for (int jj = 0; jj < 8; jj++) {
        int col = j0 + tx + 16 * jj;
#pragma unroll
        for (int p = 0; p < 4; p++) {
            float2 v = unpack2(acc[jj][p]);
            int r0 = m0 + ty * 8 + 2 * p;
            if (r0 < M)     C[r0 * ldc + col]       = v.x;
            if (r0 + 1 < M) C[(r0 + 1) * ldc + col] = v.y;
        }
    }
}

// ---------------- edge scatter: one warp per edge ----------------
// agg[dst] += m[src] * ew ; 32 lanes x float4 cover the 128-float row.
__global__ void scatter_kernel(const float* __restrict__ ea) {
    int gw   = (blockIdx.x * blockDim.x + threadIdx.x) >> 5;
    int lane = threadIdx.x & 31;
    if (gw >= EE) return;
    int s = g_src[gw];
    int d = g_dst[gw];
    float w = __ldg(&ea[gw]);
    float4 v = *((const float4*)g_m + s * 32 + lane);
    v.x *= w; v.y *= w; v.z *= w; v.w *= w;
    float* dp = g_agg + d * 128 + lane * 4;
    asm volatile("red.global.add.v4.f32 [%0], {%1, %2, %3, %4};"
                 :: "l"(dp), "f"(v.x), "f"(v.y), "f"(v.z), "f"(v.w) : "memory");
}

// ---------------- GRU gate elementwise ----------------
__global__ void gru_kernel(float* __restrict__ h) {
    int i = blockIdx.x * blockDim.x + threadIdx.x;
    if (i >= ND) return;
    int n = i >> 7, j = i & 127;
    const float* gi = g_gi + n * 384;
    const float* gh = g_gh + n * 384;
    float i_r = gi[j], i_z = gi[128 + j], i_n = gi[256 + j];
    float h_r = gh[j], h_z = gh[128 + j], h_n = gh[256 + j];
    float r = 1.f / (1.f + expf(-(i_r + h_r)));
    float z = 1.f / (1.f + expf(-(i_z + h_z)));
    float nn = tanhf(i_n + r * h_n);
    float hv = h[i];
    h[i] = (1.f - z) * nn + z * hv;
}

// ---------------- launch ----------------
extern "C" void kernel_launch(void* const* d_in, const int* in_sizes, int n_in,
                              void* d_out, int out_size) {
    const float* x    = (const float*)d_in[0];
    const int*   ei   = (const int*)d_in[1];   // int64 or int32 layout, detected on device
    const float* ea   = (const float*)d_in[2];
    const float* W    = (const float*)d_in[3];
    const float* W_ih = (const float*)d_in[4];
    const float* W_hh = (const float*)d_in[5];
    const float* b_ih = (const float*)d_in[6];
    const float* b_hh = (const float*)d_in[7];
    float* out = (float*)d_out;

    float *ph, *pm, *pagg, *pgi, *pgh, *pWt;
    cudaGetSymbolAddress((void**)&ph,   g_h);
    cudaGetSymbolAddress((void**)&pm,   g_m);
    cudaGetSymbolAddress((void**)&pagg, g_agg);
    cudaGetSymbolAddress((void**)&pgi,  g_gi);
    cudaGetSymbolAddress((void**)&pgh,  g_gh);
    cudaGetSymbolAddress((void**)&pWt,  g_Wt);

    const int n4 = ND / 4;  // 3.2M float4

    detect_kernel<<<1, 32>>>((const unsigned int*)ei);
    conv_edges_kernel<<<EE / 256, 256>>>(ei);
    copy4_kernel<<<n4 / 256, 256>>>((float4*)ph, (const float4*)x, n4);

    const int MB = (NN + 127) / 128;  // 782 row blocks

    for (int l = 0; l < 3; l++) {
        transposeW_kernel<<<64, 256>>>(W + l * DD * DD);
        gemm_bt_kernel<<<dim3(MB, 1), 256>>>(ph, pWt, nullptr, pm, NN, 128);
        zero4_kernel<<<n4 / 256, 256>>>((float4*)pagg, n4);
        scatter_kernel<<<(EE * 32) / 256, 256>>>(ea);
        gemm_bt_kernel<<<dim3(MB, 3), 256>>>(pagg, W_ih, b_ih, pgi, NN, 384);
        gemm_bt_kernel<<<dim3(MB, 3), 256>>>(ph, W_hh, b_hh, pgh, NN, 384);
        gru_kernel<<<ND / 256, 256>>>(ph);
    }

    copy4_kernel<<<n4 / 256, 256>>>((float4*)out, (const float4*)ph, n4);
}